// round 2
// baseline (speedup 1.0000x reference)
#include <cuda_runtime.h>

#define BATCH 4
#define SEQ   2048
#define NH    16
#define DH    64
#define DM    1024
#define QKVN  3072

// Scratch (device globals -- allocation-free per harness rules)
__device__ float g_q[(size_t)BATCH * NH * SEQ * DH];   // [b][h][s][dh]
__device__ float g_k[(size_t)BATCH * NH * SEQ * DH];
__device__ float g_v[(size_t)BATCH * NH * SEQ * DH];
__device__ float g_ao[(size_t)BATCH * SEQ * DM];       // [b][s][d] attn output

// ---------------------------------------------------------------------------
// Tiled SGEMM: C = A @ B^T.  A:[M,K] row-major, B:[N,K] row-major.
// 128x128 block, BK=8, 256 threads, 8x8 per-thread micro-tile.
// MODE 0: A = x param, scatter output into g_q/g_k/g_v ([b][h][s][dh]).
// MODE 1: A = g_ao (global), write C row-major.
// ---------------------------------------------------------------------------
template <int MODE>
__global__ __launch_bounds__(256) void sgemm_kernel(
    const float* __restrict__ A, const float* __restrict__ Bw,
    float* __restrict__ C, int M, int N, int K)
{
    __shared__ float As[8][128];
    __shared__ float Bs[8][128];

    const float* Ap = (MODE == 1) ? g_ao : A;

    int tid = threadIdx.x;
    int tx = tid & 15, ty = tid >> 4;
    int m0 = blockIdx.y << 7, n0 = blockIdx.x << 7;

    int lr = tid >> 1;          // 0..127: row within tile
    int lk = (tid & 1) << 2;    // 0 or 4: k offset

    const float* Aload = Ap + (size_t)(m0 + lr) * K + lk;
    const float* Bload = Bw + (size_t)(n0 + lr) * K + lk;

    float acc[8][8];
#pragma unroll
    for (int i = 0; i < 8; i++)
#pragma unroll
        for (int j = 0; j < 8; j++) acc[i][j] = 0.f;

    for (int k0 = 0; k0 < K; k0 += 8) {
        float4 av = *(const float4*)(Aload + k0);
        float4 bv = *(const float4*)(Bload + k0);
        As[lk + 0][lr] = av.x; As[lk + 1][lr] = av.y;
        As[lk + 2][lr] = av.z; As[lk + 3][lr] = av.w;
        Bs[lk + 0][lr] = bv.x; Bs[lk + 1][lr] = bv.y;
        Bs[lk + 2][lr] = bv.z; Bs[lk + 3][lr] = bv.w;
        __syncthreads();

#pragma unroll
        for (int kk = 0; kk < 8; kk++) {
            float4 a0 = *(const float4*)&As[kk][ty * 8];
            float4 a1 = *(const float4*)&As[kk][ty * 8 + 4];
            float4 b0 = *(const float4*)&Bs[kk][tx * 8];
            float4 b1 = *(const float4*)&Bs[kk][tx * 8 + 4];
            float ar[8] = {a0.x, a0.y, a0.z, a0.w, a1.x, a1.y, a1.z, a1.w};
            float br[8] = {b0.x, b0.y, b0.z, b0.w, b1.x, b1.y, b1.z, b1.w};
#pragma unroll
            for (int i = 0; i < 8; i++)
#pragma unroll
                for (int j = 0; j < 8; j++)
                    acc[i][j] += ar[i] * br[j];
        }
        __syncthreads();
    }

#pragma unroll
    for (int i = 0; i < 8; i++) {
        int m = m0 + ty * 8 + i;
        int bb = m >> 11;         // m / 2048
        int s  = m & 2047;
#pragma unroll
        for (int j = 0; j < 8; j++) {
            int n = n0 + tx * 8 + j;
            if (MODE == 0) {
                int part = n >> 10;        // 0=q, 1=k, 2=v
                int d    = n & 1023;
                int h    = d >> 6;
                int dc   = d & 63;
                size_t idx = ((((size_t)bb * NH + h) * SEQ + s) << 6) + dc;
                float* dst = (part == 0) ? g_q : (part == 1) ? g_k : g_v;
                dst[idx] = acc[i][j];
            } else {
                C[(size_t)m * N + n] = acc[i][j];
            }
        }
    }
}

// ---------------------------------------------------------------------------
// Flash attention: one block per (b, h, 64-row q-tile).
// 256 threads (16x16), 4x4 per-thread micro-tile, online softmax.
// Smem: Qs [d][r] (transposed), KPs holds K [d][c] then reused for P [p][r],
//       Vs [p][c]. Stride 68 floats (mult of 4 -> aligned float4).
// ---------------------------------------------------------------------------
#define FSTR 68
#define FLASH_SMEM_FLOATS (3 * 64 * FSTR + 128)

__global__ __launch_bounds__(256) void flash_kernel()
{
    extern __shared__ float smf[];
    float* Qs  = smf;                  // [64][FSTR] as [d][r]
    float* KPs = smf + 64 * FSTR;      // K as [d][c], then P as [p][r]
    float* Vs  = smf + 2 * 64 * FSTR;  // [p][c]
    float* m_s = smf + 3 * 64 * FSTR;  // [64]
    float* l_s = m_s + 64;             // [64]

    int qt = blockIdx.x;
    int bh = blockIdx.y;
    int b = bh >> 4, h = bh & 15;
    int tid = threadIdx.x;
    int tx = tid & 15, ty = tid >> 4;

    const float* Qg = g_q + ((size_t)bh * SEQ + (size_t)qt * 64) * DH;
    const float* Kg = g_k + (size_t)bh * SEQ * DH;
    const float* Vg = g_v + (size_t)bh * SEQ * DH;

    int lr = tid >> 2;          // 0..63 row
    int lc = (tid & 3) << 4;    // 0,16,32,48 col base

    // Load Q tile transposed into Qs[d][r]
#pragma unroll
    for (int u = 0; u < 4; u++) {
        int c = lc + u * 4;
        float4 v = *(const float4*)&Qg[lr * DH + c];
        Qs[(c + 0) * FSTR + lr] = v.x;
        Qs[(c + 1) * FSTR + lr] = v.y;
        Qs[(c + 2) * FSTR + lr] = v.z;
        Qs[(c + 3) * FSTR + lr] = v.w;
    }
    if (tid < 64) { m_s[tid] = -1e30f; l_s[tid] = 0.f; }

    float acc[4][4];
#pragma unroll
    for (int i = 0; i < 4; i++)
#pragma unroll
        for (int j = 0; j < 4; j++) acc[i][j] = 0.f;

    __syncthreads();

    for (int kt = 0; kt <= qt; kt++) {
        const float* Kt = Kg + (size_t)kt * 64 * DH;
        const float* Vt = Vg + (size_t)kt * 64 * DH;

        // Load K transposed -> KPs[d][c]; V natural -> Vs[p][c]
#pragma unroll
        for (int u = 0; u < 4; u++) {
            int c = lc + u * 4;
            float4 kv = *(const float4*)&Kt[lr * DH + c];
            KPs[(c + 0) * FSTR + lr] = kv.x;
            KPs[(c + 1) * FSTR + lr] = kv.y;
            KPs[(c + 2) * FSTR + lr] = kv.z;
            KPs[(c + 3) * FSTR + lr] = kv.w;
            *(float4*)&Vs[lr * FSTR + c] = *(const float4*)&Vt[lr * DH + c];
        }
        __syncthreads();

        // S = Q @ K^T  (4x4 per thread)
        float s[4][4];
#pragma unroll
        for (int i = 0; i < 4; i++)
#pragma unroll
            for (int j = 0; j < 4; j++) s[i][j] = 0.f;

#pragma unroll 8
        for (int d = 0; d < 64; d++) {
            float4 a  = *(const float4*)&Qs[d * FSTR + ty * 4];
            float4 k4 = *(const float4*)&KPs[d * FSTR + tx * 4];
            s[0][0] += a.x * k4.x; s[0][1] += a.x * k4.y; s[0][2] += a.x * k4.z; s[0][3] += a.x * k4.w;
            s[1][0] += a.y * k4.x; s[1][1] += a.y * k4.y; s[1][2] += a.y * k4.z; s[1][3] += a.y * k4.w;
            s[2][0] += a.z * k4.x; s[2][1] += a.z * k4.y; s[2][2] += a.z * k4.z; s[2][3] += a.z * k4.w;
            s[3][0] += a.w * k4.x; s[3][1] += a.w * k4.y; s[3][2] += a.w * k4.z; s[3][3] += a.w * k4.w;
        }
        __syncthreads();   // all warps done reading K; KPs free for P

        // scale + causal mask (diagonal tile only)
#pragma unroll
        for (int i = 0; i < 4; i++)
#pragma unroll
            for (int j = 0; j < 4; j++) s[i][j] *= 0.125f;   // 1/sqrt(64)
        if (kt == qt) {
#pragma unroll
            for (int i = 0; i < 4; i++)
#pragma unroll
                for (int j = 0; j < 4; j++)
                    if ((ty * 4 + i) < (tx * 4 + j)) s[i][j] = -1e30f;
        }

        // online softmax per row (row spans 16 lanes of the half-warp)
#pragma unroll
        for (int i = 0; i < 4; i++) {
            int row = ty * 4 + i;
            float mx = fmaxf(fmaxf(s[i][0], s[i][1]), fmaxf(s[i][2], s[i][3]));
            mx = fmaxf(mx, __shfl_xor_sync(0xffffffffu, mx, 1));
            mx = fmaxf(mx, __shfl_xor_sync(0xffffffffu, mx, 2));
            mx = fmaxf(mx, __shfl_xor_sync(0xffffffffu, mx, 4));
            mx = fmaxf(mx, __shfl_xor_sync(0xffffffffu, mx, 8));
            float mprev = m_s[row];
            float mn = fmaxf(mprev, mx);
            float p0 = __expf(s[i][0] - mn);
            float p1 = __expf(s[i][1] - mn);
            float p2 = __expf(s[i][2] - mn);
            float p3 = __expf(s[i][3] - mn);
            float rs = p0 + p1 + p2 + p3;
            rs += __shfl_xor_sync(0xffffffffu, rs, 1);
            rs += __shfl_xor_sync(0xffffffffu, rs, 2);
            rs += __shfl_xor_sync(0xffffffffu, rs, 4);
            rs += __shfl_xor_sync(0xffffffffu, rs, 8);
            float alpha = __expf(mprev - mn);
            acc[i][0] *= alpha; acc[i][1] *= alpha;
            acc[i][2] *= alpha; acc[i][3] *= alpha;
            if (tx == 0) { m_s[row] = mn; l_s[row] = l_s[row] * alpha + rs; }
            // store P transposed into KPs[p][r]
            KPs[(tx * 4 + 0) * FSTR + row] = p0;
            KPs[(tx * 4 + 1) * FSTR + row] = p1;
            KPs[(tx * 4 + 2) * FSTR + row] = p2;
            KPs[(tx * 4 + 3) * FSTR + row] = p3;
        }
        __syncthreads();   // P visible to all

        // O += P @ V
#pragma unroll 8
        for (int p = 0; p < 64; p++) {
            float4 a  = *(const float4*)&KPs[p * FSTR + ty * 4];
            float4 v4 = *(const float4*)&Vs[p * FSTR + tx * 4];
            acc[0][0] += a.x * v4.x; acc[0][1] += a.x * v4.y; acc[0][2] += a.x * v4.z; acc[0][3] += a.x * v4.w;
            acc[1][0] += a.y * v4.x; acc[1][1] += a.y * v4.y; acc[1][2] += a.y * v4.z; acc[1][3] += a.y * v4.w;
            acc[2][0] += a.z * v4.x; acc[2][1] += a.z * v4.y; acc[2][2] += a.z * v4.z; acc[2][3] += a.z * v4.w;
            acc[3][0] += a.w * v4.x; acc[3][1] += a.w * v4.y; acc[3][2] += a.w * v4.z; acc[3][3] += a.w * v4.w;
        }
        __syncthreads();   // done with P/V before next tile load
    }

    // normalize and write out: g_ao[b][s][h*64 + dh]
#pragma unroll
    for (int i = 0; i < 4; i++) {
        int row = ty * 4 + i;
        float inv = 1.f / l_s[row];
        int sq = qt * 64 + row;
        float4 o;
        o.x = acc[i][0] * inv; o.y = acc[i][1] * inv;
        o.z = acc[i][2] * inv; o.w = acc[i][3] * inv;
        *(float4*)&g_ao[((size_t)b * SEQ + sq) * DM + h * DH + tx * 4] = o;
    }
}

// ---------------------------------------------------------------------------
extern "C" void kernel_launch(void* const* d_in, const int* in_sizes, int n_in,
                              void* d_out, int out_size)
{
    const float* x    = (const float*)d_in[0];
    const float* Wqkv = (const float*)d_in[1];
    const float* Wo   = (const float*)d_in[2];
    float* out = (float*)d_out;

    constexpr size_t FLASH_SMEM = (size_t)FLASH_SMEM_FLOATS * sizeof(float);
    cudaFuncSetAttribute(flash_kernel,
                         cudaFuncAttributeMaxDynamicSharedMemorySize,
                         (int)FLASH_SMEM);

    dim3 blk(256);
    // QKV projection: [8192,1024] @ [3072,1024]^T -> scattered q/k/v
    sgemm_kernel<0><<<dim3(QKVN / 128, (BATCH * SEQ) / 128), blk>>>(
        x, Wqkv, nullptr, BATCH * SEQ, QKVN, DM);
    // Causal flash attention
    flash_kernel<<<dim3(SEQ / 64, BATCH * NH), blk, FLASH_SMEM>>>();
    // Output projection: [8192,1024] @ [1024,1024]^T -> out
    sgemm_kernel<1><<<dim3(DM / 128, (BATCH * SEQ) / 128), blk>>>(
        nullptr, Wo, out, BATCH * SEQ, DM, DM);
}

// round 4
// speedup vs baseline: 1.6591x; 1.6591x over previous
#include <cuda_runtime.h>
#include <cstdint>

#define BATCH 4
#define SEQ   2048
#define NH    16
#define DH    64
#define DM    1024
#define QKVN  3072

// Scratch (device globals -- allocation-free per harness rules)
__device__ float g_q[(size_t)BATCH * NH * SEQ * DH];   // [b][h][s][dh]
__device__ float g_k[(size_t)BATCH * NH * SEQ * DH];
__device__ float g_v[(size_t)BATCH * NH * SEQ * DH];
__device__ float g_ao[(size_t)BATCH * SEQ * DM];       // [b][s][d] attn out (tf32-rounded)
__device__ float g_xr[(size_t)BATCH * SEQ * DM];       // tf32-rounded x
__device__ float g_wr[(size_t)QKVN * DM];              // tf32-rounded W_qkv
__device__ float g_wor[(size_t)DM * DM];               // tf32-rounded W_o

// ---------------------------------------------------------------------------
// PTX helpers (portable: mma.sync + cp.async only, no 'a'-feature instructions)
// ---------------------------------------------------------------------------
__device__ __forceinline__ uint32_t smem_u32(const void* p) {
    uint32_t a;
    asm("{ .reg .u64 t; cvta.to.shared.u64 t, %1; cvt.u32.u64 %0, t; }" : "=r"(a) : "l"(p));
    return a;
}
__device__ __forceinline__ void cp_async16(uint32_t dst, const void* src) {
    asm volatile("cp.async.cg.shared.global [%0], [%1], 16;" :: "r"(dst), "l"(src) : "memory");
}
__device__ __forceinline__ void cp_commit() { asm volatile("cp.async.commit_group;" ::: "memory"); }
template <int N> __device__ __forceinline__ void cp_wait() {
    asm volatile("cp.async.wait_group %0;" :: "n"(N) : "memory");
}
__device__ __forceinline__ float rna_tf32(float x) {
    uint32_t u;
    asm("cvt.rna.tf32.f32 %0, %1;" : "=r"(u) : "f"(x));
    return __uint_as_float(u);
}
// D += A(16x8) * B(8x8), tf32 operands in b32 regs, fp32 accumulate
__device__ __forceinline__ void mma_tf32(float* d, const uint32_t* a, const uint32_t* b) {
    asm volatile(
        "mma.sync.aligned.m16n8k8.row.col.f32.tf32.tf32.f32 "
        "{%0,%1,%2,%3}, {%4,%5,%6,%7}, {%8,%9}, {%0,%1,%2,%3};"
        : "+f"(d[0]), "+f"(d[1]), "+f"(d[2]), "+f"(d[3])
        : "r"(a[0]), "r"(a[1]), "r"(a[2]), "r"(a[3]), "r"(b[0]), "r"(b[1]));
}

// ---------------------------------------------------------------------------
// Elementwise tf32 RNA round pass (mma.sync truncates raw fp32 operands)
// ---------------------------------------------------------------------------
__global__ void round_tf32_kernel(const float* __restrict__ src, float* __restrict__ dst, int n4)
{
    int i = blockIdx.x * blockDim.x + threadIdx.x;
    if (i < n4) {
        float4 v = ((const float4*)src)[i];
        v.x = rna_tf32(v.x); v.y = rna_tf32(v.y);
        v.z = rna_tf32(v.z); v.w = rna_tf32(v.w);
        ((float4*)dst)[i] = v;
    }
}

// ---------------------------------------------------------------------------
// TF32 mma.sync GEMM: C[M,N] = A[M,K] @ B[N,K]^T (both row-major).
// 128x128 CTA tile, BK=32, 8 warps in 2x4 -> 64x32 warp tile, m16n8k8.
// Smem tiles [row][k] with row stride 36 floats -> conflict-free fragment LDS.
// Double-buffered cp.async.
// MODE 0: A = param (g_xr), scatter C into g_q/g_k/g_v ([b][h][s][dh]).
// MODE 1: A = g_ao, write C row-major.
// ---------------------------------------------------------------------------
#define TSTR   36
#define TILE_F (128 * TSTR)                    // floats per tile buffer
#define GEMM_SMEM (4 * TILE_F * 4)             // A0,B0,A1,B1 = 73728 B

template <int MODE>
__global__ __launch_bounds__(256) void gemm_mma(
    const float* __restrict__ A, const float* __restrict__ Bw,
    float* __restrict__ C, int M, int N, int K)
{
    extern __shared__ float smem[];
    float* Abuf[2] = { smem,              smem + 2 * TILE_F };
    float* Bbuf[2] = { smem + TILE_F,     smem + 3 * TILE_F };
    uint32_t sbase = smem_u32(smem);

    const float* Ap = (MODE == 1) ? g_ao : A;

    int tid = threadIdx.x;
    int wid = tid >> 5, lane = tid & 31;
    int grp = lane >> 2;        // 0..7
    int thr4 = lane & 3;        // 0..3
    int wm = wid >> 2;          // 0..1  -> m offset wm*64
    int wn = wid & 3;           // 0..3  -> n offset wn*32
    int m0 = blockIdx.y << 7, n0 = blockIdx.x << 7;
    int nchunk = K >> 5;

    float acc[4][4][4];
#pragma unroll
    for (int mt = 0; mt < 4; mt++)
#pragma unroll
        for (int nt = 0; nt < 4; nt++)
#pragma unroll
            for (int e = 0; e < 4; e++) acc[mt][nt][e] = 0.f;

    auto load_chunk = [&](int chunk) {
        int buf = chunk & 1;
        uint32_t abase = sbase + (buf ? 2 * TILE_F : 0) * 4;
        uint32_t bbase = sbase + (buf ? 3 * TILE_F : 1 * TILE_F) * 4;
        int k0 = chunk << 5;
#pragma unroll
        for (int q = 0; q < 4; q++) {
            int idx = q * 256 + tid;           // 0..1023
            int row = idx >> 3, c4 = idx & 7;  // 128 rows x 8 float4
            uint32_t off = (uint32_t)(row * TSTR + c4 * 4) * 4;
            cp_async16(abase + off, Ap + (size_t)(m0 + row) * K + k0 + c4 * 4);
            cp_async16(bbase + off, Bw + (size_t)(n0 + row) * K + k0 + c4 * 4);
        }
        cp_commit();
    };

    load_chunk(0);

    for (int i = 0; i < nchunk; i++) {
        if (i + 1 < nchunk) { load_chunk(i + 1); cp_wait<1>(); }
        else                { cp_wait<0>(); }
        __syncthreads();

        const uint32_t* Au = (const uint32_t*)Abuf[i & 1];
        const uint32_t* Bu = (const uint32_t*)Bbuf[i & 1];

#pragma unroll
        for (int ks = 0; ks < 4; ks++) {
            int ka = ks * 8 + thr4;
            uint32_t afr[4][4], bfr[4][2];
#pragma unroll
            for (int mt = 0; mt < 4; mt++) {
                int r0 = wm * 64 + mt * 16 + grp;
                afr[mt][0] = Au[r0 * TSTR + ka];
                afr[mt][1] = Au[(r0 + 8) * TSTR + ka];
                afr[mt][2] = Au[r0 * TSTR + ka + 4];
                afr[mt][3] = Au[(r0 + 8) * TSTR + ka + 4];
            }
#pragma unroll
            for (int nt = 0; nt < 4; nt++) {
                int rn = wn * 32 + nt * 8 + grp;
                bfr[nt][0] = Bu[rn * TSTR + ka];
                bfr[nt][1] = Bu[rn * TSTR + ka + 4];
            }
#pragma unroll
            for (int mt = 0; mt < 4; mt++)
#pragma unroll
                for (int nt = 0; nt < 4; nt++)
                    mma_tf32(acc[mt][nt], afr[mt], bfr[nt]);
        }
        __syncthreads();   // all warps done with this buffer before reuse
    }

    // Epilogue. Lane holds C[grp][2*thr4..+1] and C[grp+8][...] per 16x8 tile.
#pragma unroll
    for (int mt = 0; mt < 4; mt++) {
#pragma unroll
        for (int nt = 0; nt < 4; nt++) {
            int m = m0 + wm * 64 + mt * 16 + grp;
            int n = n0 + wn * 32 + nt * 8 + 2 * thr4;
            float2 lo = make_float2(acc[mt][nt][0], acc[mt][nt][1]);
            float2 hi = make_float2(acc[mt][nt][2], acc[mt][nt][3]);
            if (MODE == 0) {
                int part = n >> 10;               // constant per CTA (128 | 1024)
                int d = n & 1023, h = d >> 6, dc = d & 63;
                float* dst = (part == 0) ? g_q : (part == 1) ? g_k : g_v;
                int b1 = m >> 11, s1 = m & 2047;
                *(float2*)(dst + ((((size_t)b1 * NH + h) * SEQ + s1) << 6) + dc) = lo;
                int s2 = (m + 8) & 2047;
                *(float2*)(dst + ((((size_t)b1 * NH + h) * SEQ + s2) << 6) + dc) = hi;
            } else {
                *(float2*)(C + (size_t)m * N + n) = lo;
                *(float2*)(C + (size_t)(m + 8) * N + n) = hi;
            }
        }
    }
}

// ---------------------------------------------------------------------------
// Flash attention (fp32), tf32-rounded output store (feeds tf32 proj GEMM)
// ---------------------------------------------------------------------------
#define FSTR 68
#define FLASH_SMEM_FLOATS (3 * 64 * FSTR + 128)

__global__ __launch_bounds__(256) void flash_kernel()
{
    extern __shared__ float smf[];
    float* Qs  = smf;
    float* KPs = smf + 64 * FSTR;
    float* Vs  = smf + 2 * 64 * FSTR;
    float* m_s = smf + 3 * 64 * FSTR;
    float* l_s = m_s + 64;

    int qt = blockIdx.x;
    int bh = blockIdx.y;
    int b = bh >> 4, h = bh & 15;
    int tid = threadIdx.x;
    int tx = tid & 15, ty = tid >> 4;

    const float* Qg = g_q + ((size_t)bh * SEQ + (size_t)qt * 64) * DH;
    const float* Kg = g_k + (size_t)bh * SEQ * DH;
    const float* Vg = g_v + (size_t)bh * SEQ * DH;

    int lr = tid >> 2;
    int lc = (tid & 3) << 4;

#pragma unroll
    for (int u = 0; u < 4; u++) {
        int c = lc + u * 4;
        float4 v = *(const float4*)&Qg[lr * DH + c];
        Qs[(c + 0) * FSTR + lr] = v.x;
        Qs[(c + 1) * FSTR + lr] = v.y;
        Qs[(c + 2) * FSTR + lr] = v.z;
        Qs[(c + 3) * FSTR + lr] = v.w;
    }
    if (tid < 64) { m_s[tid] = -1e30f; l_s[tid] = 0.f; }

    float acc[4][4];
#pragma unroll
    for (int i = 0; i < 4; i++)
#pragma unroll
        for (int j = 0; j < 4; j++) acc[i][j] = 0.f;

    __syncthreads();

    for (int kt = 0; kt <= qt; kt++) {
        const float* Kt = Kg + (size_t)kt * 64 * DH;
        const float* Vt = Vg + (size_t)kt * 64 * DH;

#pragma unroll
        for (int u = 0; u < 4; u++) {
            int c = lc + u * 4;
            float4 kv = *(const float4*)&Kt[lr * DH + c];
            KPs[(c + 0) * FSTR + lr] = kv.x;
            KPs[(c + 1) * FSTR + lr] = kv.y;
            KPs[(c + 2) * FSTR + lr] = kv.z;
            KPs[(c + 3) * FSTR + lr] = kv.w;
            *(float4*)&Vs[lr * FSTR + c] = *(const float4*)&Vt[lr * DH + c];
        }
        __syncthreads();

        float s[4][4];
#pragma unroll
        for (int i = 0; i < 4; i++)
#pragma unroll
            for (int j = 0; j < 4; j++) s[i][j] = 0.f;

#pragma unroll 8
        for (int d = 0; d < 64; d++) {
            float4 a  = *(const float4*)&Qs[d * FSTR + ty * 4];
            float4 k4 = *(const float4*)&KPs[d * FSTR + tx * 4];
            s[0][0] += a.x * k4.x; s[0][1] += a.x * k4.y; s[0][2] += a.x * k4.z; s[0][3] += a.x * k4.w;
            s[1][0] += a.y * k4.x; s[1][1] += a.y * k4.y; s[1][2] += a.y * k4.z; s[1][3] += a.y * k4.w;
            s[2][0] += a.z * k4.x; s[2][1] += a.z * k4.y; s[2][2] += a.z * k4.z; s[2][3] += a.z * k4.w;
            s[3][0] += a.w * k4.x; s[3][1] += a.w * k4.y; s[3][2] += a.w * k4.z; s[3][3] += a.w * k4.w;
        }
        __syncthreads();

#pragma unroll
        for (int i = 0; i < 4; i++)
#pragma unroll
            for (int j = 0; j < 4; j++) s[i][j] *= 0.125f;
        if (kt == qt) {
#pragma unroll
            for (int i = 0; i < 4; i++)
#pragma unroll
                for (int j = 0; j < 4; j++)
                    if ((ty * 4 + i) < (tx * 4 + j)) s[i][j] = -1e30f;
        }

#pragma unroll
        for (int i = 0; i < 4; i++) {
            int row = ty * 4 + i;
            float mx = fmaxf(fmaxf(s[i][0], s[i][1]), fmaxf(s[i][2], s[i][3]));
            mx = fmaxf(mx, __shfl_xor_sync(0xffffffffu, mx, 1));
            mx = fmaxf(mx, __shfl_xor_sync(0xffffffffu, mx, 2));
            mx = fmaxf(mx, __shfl_xor_sync(0xffffffffu, mx, 4));
            mx = fmaxf(mx, __shfl_xor_sync(0xffffffffu, mx, 8));
            float mprev = m_s[row];
            float mn = fmaxf(mprev, mx);
            float p0 = __expf(s[i][0] - mn);
            float p1 = __expf(s[i][1] - mn);
            float p2 = __expf(s[i][2] - mn);
            float p3 = __expf(s[i][3] - mn);
            float rs = p0 + p1 + p2 + p3;
            rs += __shfl_xor_sync(0xffffffffu, rs, 1);
            rs += __shfl_xor_sync(0xffffffffu, rs, 2);
            rs += __shfl_xor_sync(0xffffffffu, rs, 4);
            rs += __shfl_xor_sync(0xffffffffu, rs, 8);
            float alpha = __expf(mprev - mn);
            acc[i][0] *= alpha; acc[i][1] *= alpha;
            acc[i][2] *= alpha; acc[i][3] *= alpha;
            if (tx == 0) { m_s[row] = mn; l_s[row] = l_s[row] * alpha + rs; }
            KPs[(tx * 4 + 0) * FSTR + row] = p0;
            KPs[(tx * 4 + 1) * FSTR + row] = p1;
            KPs[(tx * 4 + 2) * FSTR + row] = p2;
            KPs[(tx * 4 + 3) * FSTR + row] = p3;
        }
        __syncthreads();

#pragma unroll 8
        for (int p = 0; p < 64; p++) {
            float4 a  = *(const float4*)&KPs[p * FSTR + ty * 4];
            float4 v4 = *(const float4*)&Vs[p * FSTR + tx * 4];
            acc[0][0] += a.x * v4.x; acc[0][1] += a.x * v4.y; acc[0][2] += a.x * v4.z; acc[0][3] += a.x * v4.w;
            acc[1][0] += a.y * v4.x; acc[1][1] += a.y * v4.y; acc[1][2] += a.y * v4.z; acc[1][3] += a.y * v4.w;
            acc[2][0] += a.z * v4.x; acc[2][1] += a.z * v4.y; acc[2][2] += a.z * v4.z; acc[2][3] += a.z * v4.w;
            acc[3][0] += a.w * v4.x; acc[3][1] += a.w * v4.y; acc[3][2] += a.w * v4.z; acc[3][3] += a.w * v4.w;
        }
        __syncthreads();
    }

#pragma unroll
    for (int i = 0; i < 4; i++) {
        int row = ty * 4 + i;
        float inv = 1.f / l_s[row];
        int sq = qt * 64 + row;
        float4 o;
        o.x = rna_tf32(acc[i][0] * inv); o.y = rna_tf32(acc[i][1] * inv);
        o.z = rna_tf32(acc[i][2] * inv); o.w = rna_tf32(acc[i][3] * inv);
        *(float4*)&g_ao[((size_t)b * SEQ + sq) * DM + h * DH + tx * 4] = o;
    }
}

// ---------------------------------------------------------------------------
extern "C" void kernel_launch(void* const* d_in, const int* in_sizes, int n_in,
                              void* d_out, int out_size)
{
    const float* x    = (const float*)d_in[0];
    const float* Wqkv = (const float*)d_in[1];
    const float* Wo   = (const float*)d_in[2];
    float* out = (float*)d_out;

    constexpr size_t FLASH_SMEM = (size_t)FLASH_SMEM_FLOATS * sizeof(float);
    cudaFuncSetAttribute(flash_kernel,
                         cudaFuncAttributeMaxDynamicSharedMemorySize, (int)FLASH_SMEM);
    cudaFuncSetAttribute(gemm_mma<0>,
                         cudaFuncAttributeMaxDynamicSharedMemorySize, GEMM_SMEM);
    cudaFuncSetAttribute(gemm_mma<1>,
                         cudaFuncAttributeMaxDynamicSharedMemorySize, GEMM_SMEM);

    int n4x = BATCH * SEQ * DM / 4;
    int n4w = QKVN * DM / 4;
    int n4o = DM * DM / 4;
    float* gx;  cudaGetSymbolAddress((void**)&gx,  g_xr);
    float* gw;  cudaGetSymbolAddress((void**)&gw,  g_wr);
    float* gwo; cudaGetSymbolAddress((void**)&gwo, g_wor);

    // 1) tf32-round GEMM inputs
    round_tf32_kernel<<<(n4x + 255) / 256, 256>>>(x, gx, n4x);
    round_tf32_kernel<<<(n4w + 255) / 256, 256>>>(Wqkv, gw, n4w);
    round_tf32_kernel<<<(n4o + 255) / 256, 256>>>(Wo, gwo, n4o);

    // 2) QKV projection (tf32 mma.sync): [8192,1024] @ [3072,1024]^T
    gemm_mma<0><<<dim3(QKVN / 128, (BATCH * SEQ) / 128), 256, GEMM_SMEM>>>(
        gx, gw, nullptr, BATCH * SEQ, QKVN, DM);

    // 3) Causal flash attention (fp32)
    flash_kernel<<<dim3(SEQ / 64, BATCH * NH), 256, FLASH_SMEM>>>();

    // 4) Output projection (tf32 mma.sync): [8192,1024] @ [1024,1024]^T
    gemm_mma<1><<<dim3(DM / 128, (BATCH * SEQ) / 128), 256, GEMM_SMEM>>>(
        nullptr, gwo, out, BATCH * SEQ, DM, DM);
}

// round 6
// speedup vs baseline: 3.5980x; 2.1687x over previous
#include <cuda_runtime.h>
#include <cstdint>

#define BATCH 4
#define SEQ   2048
#define NH    16
#define DH    64
#define DM    1024
#define QKVN  3072

// Scratch (device globals -- allocation-free per harness rules)
__device__ float g_q[(size_t)BATCH * NH * SEQ * DH];   // [b][h][s][dh] (tf32-rounded)
__device__ float g_k[(size_t)BATCH * NH * SEQ * DH];
__device__ float g_v[(size_t)BATCH * NH * SEQ * DH];
__device__ float g_ao[(size_t)BATCH * SEQ * DM];       // [b][s][d] attn out (tf32-rounded)
__device__ float g_xr[(size_t)BATCH * SEQ * DM];       // tf32-rounded x
__device__ float g_wr[(size_t)QKVN * DM];              // tf32-rounded W_qkv
__device__ float g_wor[(size_t)DM * DM];               // tf32-rounded W_o

// ---------------------------------------------------------------------------
// PTX helpers (portable: mma.sync + cp.async only)
// ---------------------------------------------------------------------------
__device__ __forceinline__ uint32_t smem_u32(const void* p) {
    uint32_t a;
    asm("{ .reg .u64 t; cvta.to.shared.u64 t, %1; cvt.u32.u64 %0, t; }" : "=r"(a) : "l"(p));
    return a;
}
__device__ __forceinline__ void cp_async16(uint32_t dst, const void* src) {
    asm volatile("cp.async.cg.shared.global [%0], [%1], 16;" :: "r"(dst), "l"(src) : "memory");
}
__device__ __forceinline__ void cp_commit() { asm volatile("cp.async.commit_group;" ::: "memory"); }
template <int N> __device__ __forceinline__ void cp_wait() {
    asm volatile("cp.async.wait_group %0;" :: "n"(N) : "memory");
}
__device__ __forceinline__ float rna_tf32(float x) {
    uint32_t u;
    asm("cvt.rna.tf32.f32 %0, %1;" : "=r"(u) : "f"(x));
    return __uint_as_float(u);
}
// D += A(16x8) * B(8x8), tf32 operands, fp32 accumulate
__device__ __forceinline__ void mma_tf32(float* d, const uint32_t* a, const uint32_t* b) {
    asm volatile(
        "mma.sync.aligned.m16n8k8.row.col.f32.tf32.tf32.f32 "
        "{%0,%1,%2,%3}, {%4,%5,%6,%7}, {%8,%9}, {%0,%1,%2,%3};"
        : "+f"(d[0]), "+f"(d[1]), "+f"(d[2]), "+f"(d[3])
        : "r"(a[0]), "r"(a[1]), "r"(a[2]), "r"(a[3]), "r"(b[0]), "r"(b[1]));
}

// ---------------------------------------------------------------------------
// Elementwise tf32 RNA round pass
// ---------------------------------------------------------------------------
__global__ void round_tf32_kernel(const float* __restrict__ src, float* __restrict__ dst, int n4)
{
    int i = blockIdx.x * blockDim.x + threadIdx.x;
    if (i < n4) {
        float4 v = ((const float4*)src)[i];
        v.x = rna_tf32(v.x); v.y = rna_tf32(v.y);
        v.z = rna_tf32(v.z); v.w = rna_tf32(v.w);
        ((float4*)dst)[i] = v;
    }
}

// ---------------------------------------------------------------------------
// TF32 mma.sync GEMM: C[M,N] = A[M,K] @ B[N,K]^T.  128x128 CTA tile, BK=32,
// 8 warps 2x4 -> 64x32 warp tile.  Double-buffered cp.async.
// MODE 0: scatter C into g_q/g_k/g_v with rna-tf32 rounding (feeds tf32 flash).
// MODE 1: A = g_ao, write C row-major fp32 (final output).
// ---------------------------------------------------------------------------
#define TSTR   36
#define TILE_F (128 * TSTR)
#define GEMM_SMEM (4 * TILE_F * 4)

template <int MODE>
__global__ __launch_bounds__(256, 2) void gemm_mma(
    const float* __restrict__ A, const float* __restrict__ Bw,
    float* __restrict__ C, int M, int N, int K)
{
    extern __shared__ float smem[];
    float* Abuf[2] = { smem,          smem + 2 * TILE_F };
    float* Bbuf[2] = { smem + TILE_F, smem + 3 * TILE_F };
    uint32_t sbase = smem_u32(smem);

    const float* Ap = (MODE == 1) ? g_ao : A;

    int tid = threadIdx.x;
    int wid = tid >> 5, lane = tid & 31;
    int grp = lane >> 2, thr4 = lane & 3;
    int wm = wid >> 2, wn = wid & 3;
    int m0 = blockIdx.y << 7, n0 = blockIdx.x << 7;
    int nchunk = K >> 5;

    float acc[4][4][4];
#pragma unroll
    for (int mt = 0; mt < 4; mt++)
#pragma unroll
        for (int nt = 0; nt < 4; nt++)
#pragma unroll
            for (int e = 0; e < 4; e++) acc[mt][nt][e] = 0.f;

    auto load_chunk = [&](int chunk) {
        int buf = chunk & 1;
        uint32_t abase = sbase + (buf ? 2 * TILE_F : 0) * 4;
        uint32_t bbase = sbase + (buf ? 3 * TILE_F : 1 * TILE_F) * 4;
        int k0 = chunk << 5;
#pragma unroll
        for (int q = 0; q < 4; q++) {
            int idx = q * 256 + tid;
            int row = idx >> 3, c4 = idx & 7;
            uint32_t off = (uint32_t)(row * TSTR + c4 * 4) * 4;
            cp_async16(abase + off, Ap + (size_t)(m0 + row) * K + k0 + c4 * 4);
            cp_async16(bbase + off, Bw + (size_t)(n0 + row) * K + k0 + c4 * 4);
        }
        cp_commit();
    };

    load_chunk(0);

    for (int i = 0; i < nchunk; i++) {
        if (i + 1 < nchunk) { load_chunk(i + 1); cp_wait<1>(); }
        else                { cp_wait<0>(); }
        __syncthreads();

        const uint32_t* Au = (const uint32_t*)Abuf[i & 1];
        const uint32_t* Bu = (const uint32_t*)Bbuf[i & 1];

#pragma unroll
        for (int ks = 0; ks < 4; ks++) {
            int ka = ks * 8 + thr4;
            uint32_t afr[4][4], bfr[4][2];
#pragma unroll
            for (int mt = 0; mt < 4; mt++) {
                int r0 = wm * 64 + mt * 16 + grp;
                afr[mt][0] = Au[r0 * TSTR + ka];
                afr[mt][1] = Au[(r0 + 8) * TSTR + ka];
                afr[mt][2] = Au[r0 * TSTR + ka + 4];
                afr[mt][3] = Au[(r0 + 8) * TSTR + ka + 4];
            }
#pragma unroll
            for (int nt = 0; nt < 4; nt++) {
                int rn = wn * 32 + nt * 8 + grp;
                bfr[nt][0] = Bu[rn * TSTR + ka];
                bfr[nt][1] = Bu[rn * TSTR + ka + 4];
            }
#pragma unroll
            for (int mt = 0; mt < 4; mt++)
#pragma unroll
                for (int nt = 0; nt < 4; nt++)
                    mma_tf32(acc[mt][nt], afr[mt], bfr[nt]);
        }
        __syncthreads();
    }

#pragma unroll
    for (int mt = 0; mt < 4; mt++) {
#pragma unroll
        for (int nt = 0; nt < 4; nt++) {
            int m = m0 + wm * 64 + mt * 16 + grp;
            int n = n0 + wn * 32 + nt * 8 + 2 * thr4;
            if (MODE == 0) {
                float2 lo = make_float2(rna_tf32(acc[mt][nt][0]), rna_tf32(acc[mt][nt][1]));
                float2 hi = make_float2(rna_tf32(acc[mt][nt][2]), rna_tf32(acc[mt][nt][3]));
                int part = n >> 10;
                int d = n & 1023, h = d >> 6, dc = d & 63;
                float* dst = (part == 0) ? g_q : (part == 1) ? g_k : g_v;
                int b1 = m >> 11, s1 = m & 2047;
                *(float2*)(dst + ((((size_t)b1 * NH + h) * SEQ + s1) << 6) + dc) = lo;
                int s2 = (m + 8) & 2047;
                *(float2*)(dst + ((((size_t)b1 * NH + h) * SEQ + s2) << 6) + dc) = hi;
            } else {
                *(float2*)(C + (size_t)m * N + n) =
                    make_float2(acc[mt][nt][0], acc[mt][nt][1]);
                *(float2*)(C + (size_t)(m + 8) * N + n) =
                    make_float2(acc[mt][nt][2], acc[mt][nt][3]);
            }
        }
    }
}

// ---------------------------------------------------------------------------
// Tensor-core flash attention (tf32 mma.sync).
// Q-tile 128 x K-tile 64, 8 warps; warp w owns rows [16w,16w+16) -> softmax
// is warp-local.  Strides: Q/K/P 68 (grp-row reads conflict-free), V 72
// (thr4-row reads conflict-free).
// ---------------------------------------------------------------------------
#define QSTR 68
#define VSTR 72
#define FM_SMEM ((128 * QSTR + 64 * QSTR + 64 * VSTR + 128 * QSTR) * 4)

__global__ __launch_bounds__(256, 2) void flash_mma()
{
    extern __shared__ float sm[];
    float* Qs = sm;                        // [128][68]
    float* Ks = Qs + 128 * QSTR;           // [64][68]
    float* Vs = Ks + 64 * QSTR;            // [64][72]
    float* Ps = Vs + 64 * VSTR;            // [128][68]
    uint32_t ks_base = smem_u32(Ks);
    uint32_t vs_base = smem_u32(Vs);

    int qt = blockIdx.x, bh = blockIdx.y;
    int b = bh >> 4, h = bh & 15;
    int tid = threadIdx.x, wid = tid >> 5, lane = tid & 31;
    int grp = lane >> 4 ? 0 : 0, t4 = lane & 3;   // placeholder removed below
    grp = lane >> 2;

    const float* Qg = g_q + ((size_t)bh * SEQ + (size_t)qt * 128) * DH;
    const float* Kg = g_k + (size_t)bh * SEQ * DH;
    const float* Vg = g_v + (size_t)bh * SEQ * DH;

    // Load Q tile: 128 rows x 64 cols = 2048 float4, 8 iters x 256 threads
#pragma unroll
    for (int u = 0; u < 8; u++) {
        int idx = u * 256 + tid;
        int r = idx >> 4, c4 = (idx & 15) << 2;
        *(float4*)&Qs[r * QSTR + c4] = *(const float4*)&Qg[r * DH + c4];
    }

    float accO[8][4];
#pragma unroll
    for (int nt = 0; nt < 8; nt++)
#pragma unroll
        for (int e = 0; e < 4; e++) accO[nt][e] = 0.f;
    float m0 = -1e30f, m1 = -1e30f, l0 = 0.f, l1 = 0.f;

    __syncthreads();

    int row0 = wid * 16 + grp;
    const uint32_t* Qu = (const uint32_t*)Qs;
    const uint32_t* Ku = (const uint32_t*)Ks;
    const uint32_t* Vu = (const uint32_t*)Vs;
    const uint32_t* Pu = (const uint32_t*)Ps;

    int nkt = 2 * qt + 2;
    for (int kt = 0; kt < nkt; kt++) {
        // K,V tile load: 64 rows x 64 cols = 1024 float4 each, 4 iters
#pragma unroll
        for (int u = 0; u < 4; u++) {
            int idx = u * 256 + tid;
            int r = idx >> 4, c4 = (idx & 15) << 2;
            const float* Kt = Kg + ((size_t)kt * 64 + r) * DH + c4;
            const float* Vt = Vg + ((size_t)kt * 64 + r) * DH + c4;
            cp_async16(ks_base + (uint32_t)(r * QSTR + c4) * 4, Kt);
            cp_async16(vs_base + (uint32_t)(r * VSTR + c4) * 4, Vt);
        }
        cp_commit();
        cp_wait<0>();
        __syncthreads();

        // ---- S = Q @ K^T
        float s[8][4];
#pragma unroll
        for (int nt = 0; nt < 8; nt++)
#pragma unroll
            for (int e = 0; e < 4; e++) s[nt][e] = 0.f;

#pragma unroll
        for (int ks2 = 0; ks2 < 8; ks2++) {
            int ca = ks2 * 8 + t4;
            uint32_t a[4];
            a[0] = Qu[row0 * QSTR + ca];
            a[1] = Qu[(row0 + 8) * QSTR + ca];
            a[2] = Qu[row0 * QSTR + ca + 4];
            a[3] = Qu[(row0 + 8) * QSTR + ca + 4];
#pragma unroll
            for (int nt = 0; nt < 8; nt++) {
                uint32_t bf[2];
                bf[0] = Ku[(nt * 8 + grp) * QSTR + ca];
                bf[1] = Ku[(nt * 8 + grp) * QSTR + ca + 4];
                mma_tf32(s[nt], a, bf);
            }
        }

        // ---- scale + causal mask
#pragma unroll
        for (int nt = 0; nt < 8; nt++) {
            s[nt][0] *= 0.125f; s[nt][1] *= 0.125f;
            s[nt][2] *= 0.125f; s[nt][3] *= 0.125f;
        }
        if (kt >= 2 * qt) {
            int relk = (kt - 2 * qt) * 64;
#pragma unroll
            for (int nt = 0; nt < 8; nt++) {
                int k0 = relk + nt * 8 + 2 * t4;
                if (k0 > row0)         s[nt][0] = -1e30f;
                if (k0 + 1 > row0)     s[nt][1] = -1e30f;
                if (k0 > row0 + 8)     s[nt][2] = -1e30f;
                if (k0 + 1 > row0 + 8) s[nt][3] = -1e30f;
            }
        }

        // ---- online softmax (warp-local rows)
        float tm0 = -1e30f, tm1 = -1e30f;
#pragma unroll
        for (int nt = 0; nt < 8; nt++) {
            tm0 = fmaxf(tm0, fmaxf(s[nt][0], s[nt][1]));
            tm1 = fmaxf(tm1, fmaxf(s[nt][2], s[nt][3]));
        }
        tm0 = fmaxf(tm0, __shfl_xor_sync(0xffffffffu, tm0, 1));
        tm0 = fmaxf(tm0, __shfl_xor_sync(0xffffffffu, tm0, 2));
        tm1 = fmaxf(tm1, __shfl_xor_sync(0xffffffffu, tm1, 1));
        tm1 = fmaxf(tm1, __shfl_xor_sync(0xffffffffu, tm1, 2));
        float mn0 = fmaxf(m0, tm0), mn1 = fmaxf(m1, tm1);
        float al0 = __expf(m0 - mn0), al1 = __expf(m1 - mn1);
        float rs0 = 0.f, rs1 = 0.f;
#pragma unroll
        for (int nt = 0; nt < 8; nt++) {
            float p0 = rna_tf32(__expf(s[nt][0] - mn0));
            float p1 = rna_tf32(__expf(s[nt][1] - mn0));
            float p2 = rna_tf32(__expf(s[nt][2] - mn1));
            float p3 = rna_tf32(__expf(s[nt][3] - mn1));
            rs0 += p0 + p1; rs1 += p2 + p3;
            *(float2*)&Ps[row0 * QSTR + nt * 8 + 2 * t4]       = make_float2(p0, p1);
            *(float2*)&Ps[(row0 + 8) * QSTR + nt * 8 + 2 * t4] = make_float2(p2, p3);
        }
        rs0 += __shfl_xor_sync(0xffffffffu, rs0, 1);
        rs0 += __shfl_xor_sync(0xffffffffu, rs0, 2);
        rs1 += __shfl_xor_sync(0xffffffffu, rs1, 1);
        rs1 += __shfl_xor_sync(0xffffffffu, rs1, 2);
        l0 = l0 * al0 + rs0; l1 = l1 * al1 + rs1;
        m0 = mn0; m1 = mn1;
#pragma unroll
        for (int nt = 0; nt < 8; nt++) {
            accO[nt][0] *= al0; accO[nt][1] *= al0;
            accO[nt][2] *= al1; accO[nt][3] *= al1;
        }
        __syncwarp();   // P rows are warp-private

        // ---- O += P @ V
#pragma unroll
        for (int ks2 = 0; ks2 < 8; ks2++) {
            int ca = ks2 * 8 + t4;
            uint32_t a[4];
            a[0] = Pu[row0 * QSTR + ca];
            a[1] = Pu[(row0 + 8) * QSTR + ca];
            a[2] = Pu[row0 * QSTR + ca + 4];
            a[3] = Pu[(row0 + 8) * QSTR + ca + 4];
            int vr0 = (ks2 * 8 + t4) * VSTR + grp;
            int vr1 = (ks2 * 8 + t4 + 4) * VSTR + grp;
#pragma unroll
            for (int nt = 0; nt < 8; nt++) {
                uint32_t bf[2];
                bf[0] = Vu[vr0 + nt * 8];
                bf[1] = Vu[vr1 + nt * 8];
                mma_tf32(accO[nt], a, bf);
            }
        }
        __syncthreads();   // all warps done with Ks/Vs before next load
    }

    // ---- normalize + write (tf32-rounded, feeds tf32 O-proj)
    float inv0 = 1.f / l0, inv1 = 1.f / l1;
    int sq0 = qt * 128 + row0;
    float* O0 = g_ao + ((size_t)b * SEQ + sq0) * DM + h * DH;
    float* O1 = g_ao + ((size_t)b * SEQ + sq0 + 8) * DM + h * DH;
#pragma unroll
    for (int nt = 0; nt < 8; nt++) {
        int c = nt * 8 + 2 * t4;
        *(float2*)&O0[c] = make_float2(rna_tf32(accO[nt][0] * inv0),
                                       rna_tf32(accO[nt][1] * inv0));
        *(float2*)&O1[c] = make_float2(rna_tf32(accO[nt][2] * inv1),
                                       rna_tf32(accO[nt][3] * inv1));
    }
}

// ---------------------------------------------------------------------------
extern "C" void kernel_launch(void* const* d_in, const int* in_sizes, int n_in,
                              void* d_out, int out_size)
{
    const float* x    = (const float*)d_in[0];
    const float* Wqkv = (const float*)d_in[1];
    const float* Wo   = (const float*)d_in[2];
    float* out = (float*)d_out;

    cudaFuncSetAttribute(flash_mma,
                         cudaFuncAttributeMaxDynamicSharedMemorySize, FM_SMEM);
    cudaFuncSetAttribute(gemm_mma<0>,
                         cudaFuncAttributeMaxDynamicSharedMemorySize, GEMM_SMEM);
    cudaFuncSetAttribute(gemm_mma<1>,
                         cudaFuncAttributeMaxDynamicSharedMemorySize, GEMM_SMEM);

    int n4x = BATCH * SEQ * DM / 4;
    int n4w = QKVN * DM / 4;
    int n4o = DM * DM / 4;
    float* gx;  cudaGetSymbolAddress((void**)&gx,  g_xr);
    float* gw;  cudaGetSymbolAddress((void**)&gw,  g_wr);
    float* gwo; cudaGetSymbolAddress((void**)&gwo, g_wor);

    // 1) tf32-round GEMM inputs
    round_tf32_kernel<<<(n4x + 255) / 256, 256>>>(x, gx, n4x);
    round_tf32_kernel<<<(n4w + 255) / 256, 256>>>(Wqkv, gw, n4w);
    round_tf32_kernel<<<(n4o + 255) / 256, 256>>>(Wo, gwo, n4o);

    // 2) QKV projection (tf32 mma.sync)
    gemm_mma<0><<<dim3(QKVN / 128, (BATCH * SEQ) / 128), 256, GEMM_SMEM>>>(
        gx, gw, nullptr, BATCH * SEQ, QKVN, DM);

    // 3) Causal flash attention (tf32 mma.sync)
    flash_mma<<<dim3(SEQ / 128, BATCH * NH), 256, FM_SMEM>>>();

    // 4) Output projection (tf32 mma.sync)
    gemm_mma<1><<<dim3(DM / 128, (BATCH * SEQ) / 128), 256, GEMM_SMEM>>>(
        nullptr, gwo, out, BATCH * SEQ, DM, DM);
}